// round 1
// baseline (speedup 1.0000x reference)
#include <cuda_runtime.h>
#include <math.h>

#define THREADS 64
#define ROWS    64      // q rows per block = threads (one row per thread)
#define TN      64      // kv tile rows
#define D       64
#define LQ      2048
#define LKV     2048
#define BATCH   16

// ---- packed f32x2 helpers (sm_103a paired FP32 pipe) ----
__device__ __forceinline__ unsigned long long fma2(unsigned long long a,
                                                   unsigned long long b,
                                                   unsigned long long c) {
    unsigned long long d;
    asm("fma.rn.f32x2 %0, %1, %2, %3;" : "=l"(d) : "l"(a), "l"(b), "l"(c));
    return d;
}
__device__ __forceinline__ unsigned long long add2(unsigned long long a,
                                                   unsigned long long b) {
    unsigned long long d;
    asm("add.rn.f32x2 %0, %1, %2;" : "=l"(d) : "l"(a), "l"(b));
    return d;
}
__device__ __forceinline__ unsigned long long mul2(unsigned long long a,
                                                   unsigned long long b) {
    unsigned long long d;
    asm("mul.rn.f32x2 %0, %1, %2;" : "=l"(d) : "l"(a), "l"(b));
    return d;
}
__device__ __forceinline__ unsigned long long pack2(float lo, float hi) {
    unsigned long long d;
    asm("mov.b64 %0, {%1, %2};" : "=l"(d) : "r"(__float_as_uint(lo)), "r"(__float_as_uint(hi)));
    return d;
}
__device__ __forceinline__ void unpack2(unsigned long long a, float& lo, float& hi) {
    unsigned int x, y;
    asm("mov.b64 {%0, %1}, %2;" : "=r"(x), "=r"(y) : "l"(a));
    lo = __uint_as_float(x);
    hi = __uint_as_float(y);
}

__global__ __launch_bounds__(THREADS)
void sdpa_f32x2_kernel(const float* __restrict__ q,
                       const float* __restrict__ k,
                       const float* __restrict__ v,
                       float* __restrict__ out) {
    // K/V tiles as packed f32x2 words: TN rows x (D/2) packed words
    __shared__ unsigned long long Ks[TN * (D / 2)];
    __shared__ unsigned long long Vs[TN * (D / 2)];

    const int b   = blockIdx.y;
    const int row = blockIdx.x * ROWS + threadIdx.x;

    // Load this thread's Q row into registers (32 packed f32x2)
    const unsigned long long* qp =
        (const unsigned long long*)(q + ((size_t)b * LQ + row) * D);
    unsigned long long q2[D / 2];
#pragma unroll
    for (int i = 0; i < D / 2; i++) q2[i] = qp[i];

    unsigned long long O2[D / 2];
#pragma unroll
    for (int i = 0; i < D / 2; i++) O2[i] = 0ull;

    float m = -INFINITY;
    float l = 0.0f;
    const float inv_scale = 0.125f;  // 1 / scale_factor (= 1/8)

    const float* kb = k + (size_t)b * LKV * D;
    const float* vb = v + (size_t)b * LKV * D;

    for (int t = 0; t < LKV; t += TN) {
        __syncthreads();
        // Cooperative coalesced tile load (16B per thread per iteration)
        {
            const ulonglong2* kg = (const ulonglong2*)(kb + (size_t)t * D);
            const ulonglong2* vg = (const ulonglong2*)(vb + (size_t)t * D);
            ulonglong2* Ks2 = (ulonglong2*)Ks;
            ulonglong2* Vs2 = (ulonglong2*)Vs;
            const int n128 = TN * D / 4;  // 1024 16B chunks per tile
#pragma unroll
            for (int it = 0; it < n128 / THREADS; it++) {
                int idx = threadIdx.x + it * THREADS;
                Ks2[idx] = kg[idx];
                Vs2[idx] = vg[idx];
            }
        }
        __syncthreads();

        for (int j = 0; j < TN; j++) {
            const unsigned long long* kr = Ks + j * (D / 2);
            // Q . K_j with 4 packed accumulators
            unsigned long long a0 = 0ull, a1 = 0ull, a2 = 0ull, a3 = 0ull;
#pragma unroll
            for (int i = 0; i < D / 2; i += 4) {
                a0 = fma2(q2[i + 0], kr[i + 0], a0);
                a1 = fma2(q2[i + 1], kr[i + 1], a1);
                a2 = fma2(q2[i + 2], kr[i + 2], a2);
                a3 = fma2(q2[i + 3], kr[i + 3], a3);
            }
            a0 = add2(add2(a0, a1), add2(a2, a3));
            float sx, sy;
            unpack2(a0, sx, sy);
            float s = (sx + sy) * inv_scale;

            const unsigned long long* vr = Vs + j * (D / 2);
            if (s <= m) {
                // common path: no new max
                float p = __expf(s - m);
                l += p;
                unsigned long long pp = pack2(p, p);
#pragma unroll
                for (int i = 0; i < D / 2; i++) O2[i] = fma2(pp, vr[i], O2[i]);
            } else {
                // rare path: new running max -> rescale (p_new = 1)
                float c = __expf(m - s);
                m = s;
                l = l * c + 1.0f;
                unsigned long long cc = pack2(c, c);
#pragma unroll
                for (int i = 0; i < D / 2; i++) O2[i] = fma2(cc, O2[i], vr[i]);
            }
        }
    }

    const float inv_l = 1.0f / l;
    unsigned long long il = pack2(inv_l, inv_l);
    unsigned long long* op =
        (unsigned long long*)(out + ((size_t)b * LQ + row) * D);
#pragma unroll
    for (int i = 0; i < D / 2; i++) op[i] = mul2(O2[i], il);
}

extern "C" void kernel_launch(void* const* d_in, const int* in_sizes, int n_in,
                              void* d_out, int out_size) {
    const float* q = (const float*)d_in[0];
    const float* k = (const float*)d_in[1];
    const float* v = (const float*)d_in[2];
    float* out = (float*)d_out;
    (void)in_sizes; (void)n_in; (void)out_size;

    dim3 grid(LQ / ROWS, BATCH);  // (32, 16) = 512 blocks
    dim3 block(THREADS);
    sdpa_f32x2_kernel<<<grid, block>>>(q, k, v, out);
}

// round 6
// speedup vs baseline: 5.5028x; 5.5028x over previous
#include <cuda_runtime.h>
#include <stdint.h>

#define BATCH 16
#define LQ 2048
#define LKV 2048
#define DH 64
#define BM 128
#define BN 64
#define NT (LKV / BN)      // 32
#define THREADS 128
#define KSTR 68            // K smem row stride (floats): conflict-free B-frag loads
#define VSTR 72            // V smem row stride
#define PSTR 68            // P / staged-Q row stride

#define OFF_K 0
#define OFF_V (64 * KSTR)
#define OFF_P (OFF_V + 64 * VSTR)
#define SMEM_FLOATS (OFF_P + 4 * 32 * PSTR)
#define SMEM_BYTES (SMEM_FLOATS * 4)   // 70656 B

__device__ __forceinline__ float ex2f(float x) {
    float y; asm("ex2.approx.ftz.f32 %0, %1;" : "=f"(y) : "f"(x)); return y;
}
__device__ __forceinline__ uint32_t tf32(float x) {
    uint32_t y; asm("cvt.rna.tf32.f32 %0, %1;" : "=r"(y) : "f"(x)); return y;
}
__device__ __forceinline__ void mma8(float* d, const uint32_t* a, const uint32_t* b) {
    asm volatile(
        "mma.sync.aligned.m16n8k8.row.col.f32.tf32.tf32.f32 "
        "{%0,%1,%2,%3}, {%4,%5,%6,%7}, {%8,%9}, {%0,%1,%2,%3};"
        : "+f"(d[0]), "+f"(d[1]), "+f"(d[2]), "+f"(d[3])
        : "r"(a[0]), "r"(a[1]), "r"(a[2]), "r"(a[3]), "r"(b[0]), "r"(b[1]));
}

__global__ void __launch_bounds__(THREADS, 2)
sdpa_mma(const float* __restrict__ qg, const float* __restrict__ kg,
         const float* __restrict__ vg, float* __restrict__ out) {
    extern __shared__ float sm[];
    const int tid = threadIdx.x;
    const int w = tid >> 5, l = tid & 31;
    const int g = l >> 2, tg = l & 3;          // quad row / quad lane
    const int b = blockIdx.y;
    const int q0 = blockIdx.x * BM;

    float* Ks = sm + OFF_K;
    float* Vs = sm + OFF_V;
    uint32_t* Pw = (uint32_t*)(sm + OFF_P) + w * 32 * PSTR;  // this warp's 32 rows

    // ---- stage Q (scale folded, tf32-rounded) into the P region ----
    {
        const float QS = 0.18033688011112042f;  // log2(e) / 8
        const float* qp = qg + ((size_t)b * LQ + q0) * DH;
        uint32_t* Pq = (uint32_t*)(sm + OFF_P);
#pragma unroll
        for (int it = 0; it < 16; it++) {
            int idx = it * THREADS + tid;      // 128 rows x 16 float4-groups
            int row = idx >> 4, c = (idx & 15) << 2;
            float4 x = *(const float4*)(qp + row * DH + c);
            uint4 y;
            y.x = tf32(x.x * QS); y.y = tf32(x.y * QS);
            y.z = tf32(x.z * QS); y.w = tf32(x.w * QS);
            *(uint4*)(Pq + (row >> 5) * (32 * PSTR) + (row & 31) * PSTR + c) = y;
        }
    }
    __syncthreads();

    // ---- load persistent Q A-fragments (m32 = two m16 chunks) ----
    uint32_t Qa[2][8][4];
#pragma unroll
    for (int i = 0; i < 2; i++)
#pragma unroll
        for (int kc = 0; kc < 8; kc++) {
            int base = (i * 16 + g) * PSTR + kc * 8 + tg;
            Qa[i][kc][0] = Pw[base];
            Qa[i][kc][1] = Pw[base + 8 * PSTR];
            Qa[i][kc][2] = Pw[base + 4];
            Qa[i][kc][3] = Pw[base + 8 * PSTR + 4];
        }

    float O[2][8][4];
#pragma unroll
    for (int i = 0; i < 2; i++)
#pragma unroll
        for (int n = 0; n < 8; n++)
#pragma unroll
            for (int j = 0; j < 4; j++) O[i][n][j] = 0.f;
    float ls[4] = {0.f, 0.f, 0.f, 0.f};

    const float* kb = kg + (size_t)b * LKV * DH;
    const float* vb = vg + (size_t)b * LKV * DH;
    const uint32_t* Ksu = (const uint32_t*)Ks;
    const uint32_t* Vsu = (const uint32_t*)Vs;

    for (int t = 0; t < NT; t++) {
        __syncthreads();  // previous tile's PV done in all warps
        // ---- cooperative K/V tile load + tf32 convert ----
        // BN(64) rows x 16 float4-groups = 1024 groups -> 8 iters x 128 thr
#pragma unroll
        for (int it = 0; it < 8; it++) {
            int idx = it * THREADS + tid;        // 0..1023
            int row = idx >> 4, c = (idx & 15) << 2;
            float4 x = *(const float4*)(kb + ((size_t)t * BN + row) * DH + c);
            uint4 y;
            y.x = tf32(x.x); y.y = tf32(x.y); y.z = tf32(x.z); y.w = tf32(x.w);
            *(uint4*)((uint32_t*)Ks + row * KSTR + c) = y;
            float4 xv = *(const float4*)(vb + ((size_t)t * BN + row) * DH + c);
            uint4 yv;
            yv.x = tf32(xv.x); yv.y = tf32(xv.y); yv.z = tf32(xv.z); yv.w = tf32(xv.w);
            *(uint4*)((uint32_t*)Vs + row * VSTR + c) = yv;
        }
        __syncthreads();

        // ---- S = Q.K^T (tf32 mma), softmax exp, P -> smem ----
#pragma unroll
        for (int nc = 0; nc < 8; nc++) {
            float s0[4] = {0.f, 0.f, 0.f, 0.f};
            float s1[4] = {0.f, 0.f, 0.f, 0.f};
#pragma unroll
            for (int kc = 0; kc < 8; kc++) {
                uint32_t bb[2];
                int ba = (nc * 8 + g) * KSTR + kc * 8 + tg;
                bb[0] = Ksu[ba];
                bb[1] = Ksu[ba + 4];
                mma8(s0, Qa[0][kc], bb);
                mma8(s1, Qa[1][kc], bb);
            }
            float p00 = ex2f(s0[0]), p01 = ex2f(s0[1]);
            float p02 = ex2f(s0[2]), p03 = ex2f(s0[3]);
            float p10 = ex2f(s1[0]), p11 = ex2f(s1[1]);
            float p12 = ex2f(s1[2]), p13 = ex2f(s1[3]);
            ls[0] += p00 + p01; ls[1] += p02 + p03;
            ls[2] += p10 + p11; ls[3] += p12 + p13;
            int pa = g * PSTR + nc * 8 + 2 * tg;
            *(uint2*)(Pw + pa)             = make_uint2(tf32(p00), tf32(p01));
            *(uint2*)(Pw + pa + 8 * PSTR)  = make_uint2(tf32(p02), tf32(p03));
            *(uint2*)(Pw + pa + 16 * PSTR) = make_uint2(tf32(p10), tf32(p11));
            *(uint2*)(Pw + pa + 24 * PSTR) = make_uint2(tf32(p12), tf32(p13));
        }
        __syncwarp();  // P produced & consumed within this warp only

        // ---- O += P.V (tf32 mma) ----
#pragma unroll
        for (int kc = 0; kc < 8; kc++) {
            uint32_t a0[4], a1[4];
            int base = g * PSTR + kc * 8 + tg;
            a0[0] = Pw[base];
            a0[1] = Pw[base + 8 * PSTR];
            a0[2] = Pw[base + 4];
            a0[3] = Pw[base + 8 * PSTR + 4];
            int b1 = base + 16 * PSTR;
            a1[0] = Pw[b1];
            a1[1] = Pw[b1 + 8 * PSTR];
            a1[2] = Pw[b1 + 4];
            a1[3] = Pw[b1 + 8 * PSTR + 4];
#pragma unroll
            for (int nc = 0; nc < 8; nc++) {
                uint32_t bb[2];
                int ba = (kc * 8 + tg) * VSTR + nc * 8 + g;
                bb[0] = Vsu[ba];
                bb[1] = Vsu[ba + 4 * VSTR];
                mma8(O[0][nc], a0, bb);
                mma8(O[1][nc], a1, bb);
            }
        }
    }

    // ---- row-sum reduce across the 4-lane quad, write out ----
#pragma unroll
    for (int j = 0; j < 4; j++) {
        ls[j] += __shfl_xor_sync(0xffffffffu, ls[j], 1);
        ls[j] += __shfl_xor_sync(0xffffffffu, ls[j], 2);
    }
    float inv[4] = {1.f / ls[0], 1.f / ls[1], 1.f / ls[2], 1.f / ls[3]};
    float* ob = out + ((size_t)b * LQ + q0 + w * 32) * DH;
#pragma unroll
    for (int i = 0; i < 2; i++) {
        int r01 = i * 16 + g, r23 = r01 + 8;
#pragma unroll
        for (int nc = 0; nc < 8; nc++) {
            int c = nc * 8 + 2 * tg;
            float2 v01 = {O[i][nc][0] * inv[2 * i], O[i][nc][1] * inv[2 * i]};
            float2 v23 = {O[i][nc][2] * inv[2 * i + 1], O[i][nc][3] * inv[2 * i + 1]};
            *(float2*)(ob + r01 * DH + c) = v01;
            *(float2*)(ob + r23 * DH + c) = v23;
        }
    }
}

extern "C" void kernel_launch(void* const* d_in, const int* in_sizes, int n_in,
                              void* d_out, int out_size) {
    const float* q = (const float*)d_in[0];
    const float* k = (const float*)d_in[1];
    const float* v = (const float*)d_in[2];
    float* out = (float*)d_out;
    (void)in_sizes; (void)n_in; (void)out_size;

    cudaFuncSetAttribute(sdpa_mma, cudaFuncAttributeMaxDynamicSharedMemorySize,
                         SMEM_BYTES);
    dim3 grid(LQ / BM, BATCH);  // (16, 16)
    sdpa_mma<<<grid, THREADS, SMEM_BYTES>>>(q, k, v, out);
}